// round 12
// baseline (speedup 1.0000x reference)
#include <cuda_runtime.h>
#include <cuda_bf16.h>
#include <math.h>
#include <stdint.h>

#define Bb 4
#define Cc 128
#define Kk 64
#define Hh 256
#define Ww 256
#define HW (Hh*Ww)
#define NT 256          // B * P*P tiles
#define LDB 72          // bf16 elements per smem row (64 data + 8 pad)
#define GRAM2_SMEM 73728
#define OUT3_SMEM 198912
#define MID2_SMEM 211200

typedef unsigned short ush;

// ---- mma.sync helpers (arch-neutral tensor path) ----
__device__ __forceinline__ uint32_t s2u(const void* p){
    uint32_t a;
    asm("{ .reg .u64 t; cvta.to.shared.u64 t, %1; cvt.u32.u64 %0, t; }" : "=r"(a) : "l"(p));
    return a;
}
__device__ __forceinline__ void ldm4(uint32_t* d, uint32_t addr){
    asm volatile("ldmatrix.sync.aligned.m8n8.x4.shared.b16 {%0,%1,%2,%3}, [%4];"
        : "=r"(d[0]), "=r"(d[1]), "=r"(d[2]), "=r"(d[3]) : "r"(addr));
}
__device__ __forceinline__ void ldm4t(uint32_t* d, uint32_t addr){
    asm volatile("ldmatrix.sync.aligned.m8n8.x4.trans.shared.b16 {%0,%1,%2,%3}, [%4];"
        : "=r"(d[0]), "=r"(d[1]), "=r"(d[2]), "=r"(d[3]) : "r"(addr));
}
__device__ __forceinline__ void mma16816(float* c, const uint32_t* a, const uint32_t* b){
    asm volatile("mma.sync.aligned.m16n8k16.row.col.f32.bf16.bf16.f32 "
        "{%0,%1,%2,%3}, {%4,%5,%6,%7}, {%8,%9}, {%0,%1,%2,%3};"
        : "+f"(c[0]), "+f"(c[1]), "+f"(c[2]), "+f"(c[3])
        : "r"(a[0]), "r"(a[1]), "r"(a[2]), "r"(a[3]), "r"(b[0]), "r"(b[1]));
}
__device__ __forceinline__ uint32_t bfp(__nv_bfloat16 a, __nv_bfloat16 b){
    return ((uint32_t)__bfloat16_as_ushort(b) << 16) | (uint32_t)__bfloat16_as_ushort(a);
}
__device__ __forceinline__ uint32_t bfp2(float a, float b){
    return bfp(__float2bfloat16(a), __float2bfloat16(b));
}

// Scratch (allocation-free rule: __device__ globals)
__device__ float dG[2*NT*Cc*Cc];   // per (stream,tile) Gram 128x128
__device__ float dS[2*NT*Cc];      // per (stream,tile) row sums
__device__ ush   dAh[2*NT*Cc*Kk];  // A hi bf16, layout [s][t][o=128][k=64]
__device__ ush   dAl[2*NT*Cc*Kk];  // A lo bf16

// ---------------------------------------------------------------------------
// Kernel A (HMMA): G = X X^T with symmetric 2-product split:
//   G = HH + Q' + Q'^T,  HH = Xhi Xhi^T,  Q' = Xlo Xhi^T  (lo on the A side:
//   2 lo-ldm4 per kstep instead of 4 -> 20% less ldmatrix traffic)
// ---------------------------------------------------------------------------
__global__ __launch_bounds__(256) void gram_kernel(const float* __restrict__ x1,
                                                   const float* __restrict__ x2)
{
    extern __shared__ char gsm[];
    uint32_t gb = s2u(gsm);

    int t = blockIdx.x, s = blockIdx.y;
    const float* x = s ? x2 : x1;
    int b = t >> 6, q = t & 63;
    int pi = q >> 3, pj = q & 7;
    long base0 = (long)b*Cc*HW + (long)(pi*32)*Ww + pj*32;

    int tid = threadIdx.x, wid = tid >> 5, lane = tid & 31;
    int c0 = tid >> 1, half = tid & 1;
    const float* rowbase = x + base0 + (long)c0*HW + (long)half*Ww;

    int wm = wid & 3, wn = wid >> 2;
    int m0 = wm*32, n0 = wn*64;

    float acc_hh[2][8][4], acc_q[2][8][4];
    #pragma unroll
    for (int a = 0; a < 2; a++)
        #pragma unroll
        for (int nt = 0; nt < 8; nt++)
            #pragma unroll
            for (int e = 0; e < 4; e++) { acc_hh[a][nt][e] = 0.f; acc_q[a][nt][e] = 0.f; }

    float ps = 0.f;
    float4 pref[8];
    {
        const float4* src = (const float4*)rowbase;
        #pragma unroll
        for (int j = 0; j < 8; j++) pref[j] = src[j];
    }

    uint32_t aRow = (uint32_t)(lane & 15);
    uint32_t aKof = (uint32_t)((lane >> 4) << 3);
    uint32_t bRow = (uint32_t)((lane & 7) + ((lane >> 4) << 3));
    uint32_t bKof = (uint32_t)(((lane >> 3) & 1) << 3);

    uint32_t wo = ((uint32_t)c0*LDB + (uint32_t)half*32u)*2u;

    #pragma unroll
    for (int j = 0; j < 8; j++) {
        float4 v = pref[j];
        ps += (v.x + v.y) + (v.z + v.w);
        __nv_bfloat16 hx = __float2bfloat16(v.x), hy = __float2bfloat16(v.y),
                      hz = __float2bfloat16(v.z), hw = __float2bfloat16(v.w);
        uint32_t off = wo + 8u*j;
        *(uint2*)(gsm + off) = make_uint2(bfp(hx, hy), bfp(hz, hw));
        *(uint2*)(gsm + 18432 + off) = make_uint2(
            bfp2(v.x - __bfloat162float(hx), v.y - __bfloat162float(hy)),
            bfp2(v.z - __bfloat162float(hz), v.w - __bfloat162float(hw)));
    }
    {
        const float4* src = (const float4*)(rowbase + (long)2*Ww);
        #pragma unroll
        for (int j = 0; j < 8; j++) pref[j] = src[j];
    }
    __syncthreads();

    for (int ch = 0; ch < 16; ch++) {
        uint32_t hiB = gb + (uint32_t)(ch & 1)*36864u;
        uint32_t loB = hiB + 18432u;

        #pragma unroll
        for (int ks = 0; ks < 4; ks++) {
            uint32_t k0 = (uint32_t)(ks*16);
            uint32_t ahi[2][4], alo[2][4], bhi[8][2];
            #pragma unroll
            for (int a = 0; a < 2; a++) {
                uint32_t eo = ((uint32_t)(m0 + a*16) + aRow)*LDB + k0 + aKof;
                ldm4(ahi[a], hiB + eo*2u);
                ldm4(alo[a], loB + eo*2u);
            }
            #pragma unroll
            for (int p = 0; p < 4; p++) {
                uint32_t eo = ((uint32_t)(n0 + p*16) + bRow)*LDB + k0 + bKof;
                uint32_t r[4];
                ldm4(r, hiB + eo*2u);
                bhi[2*p][0] = r[0]; bhi[2*p][1] = r[1];
                bhi[2*p+1][0] = r[2]; bhi[2*p+1][1] = r[3];
            }
            #pragma unroll
            for (int a = 0; a < 2; a++)
                #pragma unroll
                for (int nt = 0; nt < 8; nt++) {
                    mma16816(acc_hh[a][nt], ahi[a], bhi[nt]);
                    mma16816(acc_q[a][nt],  alo[a], bhi[nt]);
                }
        }

        if (ch < 15) {
            char* dsth = gsm + ((ch + 1) & 1)*36864;
            #pragma unroll
            for (int j = 0; j < 8; j++) {
                float4 v = pref[j];
                ps += (v.x + v.y) + (v.z + v.w);
                __nv_bfloat16 hx = __float2bfloat16(v.x), hy = __float2bfloat16(v.y),
                              hz = __float2bfloat16(v.z), hw = __float2bfloat16(v.w);
                uint32_t off = wo + 8u*j;
                *(uint2*)(dsth + off) = make_uint2(bfp(hx, hy), bfp(hz, hw));
                *(uint2*)(dsth + 18432 + off) = make_uint2(
                    bfp2(v.x - __bfloat162float(hx), v.y - __bfloat162float(hy)),
                    bfp2(v.z - __bfloat162float(hz), v.w - __bfloat162float(hw)));
            }
            if (ch < 14) {
                const float4* src = (const float4*)(rowbase + (long)((ch + 2)*2)*Ww);
                #pragma unroll
                for (int j = 0; j < 8; j++) pref[j] = src[j];
            }
        }
        __syncthreads();
    }

    // epilogue: G = HH + Q' + Q'^T
    {
        float* Qs = (float*)gsm;
        int grp = lane >> 2, tix = lane & 3;
        #pragma unroll
        for (int a = 0; a < 2; a++)
            #pragma unroll
            for (int nt = 0; nt < 8; nt++) {
                int r0 = m0 + a*16 + grp, cc = n0 + nt*8 + tix*2;
                Qs[r0*132 + cc]       = acc_q[a][nt][0];
                Qs[r0*132 + cc + 1]   = acc_q[a][nt][1];
                Qs[(r0+8)*132 + cc]   = acc_q[a][nt][2];
                Qs[(r0+8)*132 + cc+1] = acc_q[a][nt][3];
            }
        __syncthreads();
        float* Gout = dG + (long)(s*NT + t)*(Cc*Cc);
        #pragma unroll
        for (int a = 0; a < 2; a++)
            #pragma unroll
            for (int nt = 0; nt < 8; nt++) {
                int r0 = m0 + a*16 + grp, cc = n0 + nt*8 + tix*2;
                float2 v0, v1;
                v0.x = acc_hh[a][nt][0] + acc_q[a][nt][0] + Qs[cc*132 + r0];
                v0.y = acc_hh[a][nt][1] + acc_q[a][nt][1] + Qs[(cc+1)*132 + r0];
                v1.x = acc_hh[a][nt][2] + acc_q[a][nt][2] + Qs[cc*132 + r0 + 8];
                v1.y = acc_hh[a][nt][3] + acc_q[a][nt][3] + Qs[(cc+1)*132 + r0 + 8];
                *(float2*)(Gout + (long)r0*128 + cc)       = v0;
                *(float2*)(Gout + (long)(r0 + 8)*128 + cc) = v1;
            }
    }

    {
        float tot = ps + __shfl_xor_sync(0xffffffffu, ps, 1);
        if (half == 0) dS[(s*NT + t)*Cc + c0] = tot;
    }
}

// ---------------------------------------------------------------------------
// Kernel B v2 (HMMA): three tensor-core GEMMs with bf16 hi/lo 3-product.
//   T1 = W1 @ G   (G symmetric -> B operand reads stored layout directly)
//   M  = T1 @ W2^T + rank-1 bias terms
//   u  = M / (1e-6 + colnorm);   A = Wout @ u  -> dAh/dAl [o][k]
// smem plan (bytes):
//   R1 @0      (69632): Gh/Gl -> after GEMM1: W2h/W2l (34816) + M fp32 (34816)
//   R2 @69632  (69632): W1h/W1l -> T1h/T1l -> u^T h/l (34816)
//   R3 @139264 (69632): Wout h/l
//   extras @208896: sS[128], b1[128], b2[64], w1s[128], w2s[64], nk[64]
// ---------------------------------------------------------------------------
__global__ __launch_bounds__(256) void mid_kernel(
    const float* __restrict__ W1a, const float* __restrict__ B1a,
    const float* __restrict__ W2a, const float* __restrict__ B2a,
    const float* __restrict__ Wouta,
    const float* __restrict__ W1b, const float* __restrict__ B1b,
    const float* __restrict__ W2b, const float* __restrict__ B2b,
    const float* __restrict__ Woutb)
{
    extern __shared__ char msm[];
    ush* sGh  = (ush*)msm;                 // [128][136]
    ush* sGl  = (ush*)(msm + 34816);
    ush* sT1h = (ush*)(msm + 69632);       // W1 then T1 then (u^T in first 17408B*2)
    ush* sT1l = (ush*)(msm + 104448);
    ush* sWoh = (ush*)(msm + 139264);
    ush* sWol = (ush*)(msm + 174080);
    ush* sW2h = (ush*)msm;                 // overlays G after GEMM1: [64][136]
    ush* sW2l = (ush*)(msm + 17408);
    float* sM = (float*)(msm + 34816);     // [128][68] fp32
    ush* sUh  = (ush*)(msm + 69632);       // overlays T1 after GEMM2: [64][136]
    ush* sUl  = (ush*)(msm + 87040);
    float* sS  = (float*)(msm + 208896);   // 128
    float* sb1 = sS + 128;                 // 128
    float* sb2 = sb1 + 128;                // 64
    float* w1s = sb2 + 64;                 // 128
    float* w2s = w1s + 128;                // 64
    float* nk  = w2s + 64;                 // 64

    uint32_t uGh = s2u(sGh), uGl = s2u(sGl);
    uint32_t uT1h = s2u(sT1h), uT1l = s2u(sT1l);
    uint32_t uWoh = s2u(sWoh), uWol = s2u(sWol);
    uint32_t uW2h = s2u(sW2h), uW2l = s2u(sW2l);
    uint32_t uUh = s2u(sUh), uUl = s2u(sUl);

    int s = blockIdx.y;
    const float* W1   = s ? W1b   : W1a;
    const float* B1   = s ? B1b   : B1a;
    const float* W2   = s ? W2b   : W2a;
    const float* B2   = s ? B2b   : B2a;
    const float* Wout = s ? Woutb : Wouta;

    int t = blockIdx.x, tid = threadIdx.x, wid = tid >> 5, lane = tid & 31;
    const float* Gsrc = dG + (long)(s*NT + t)*(Cc*Cc);

    uint32_t aRow = (uint32_t)(lane & 15);
    uint32_t aKof = (uint32_t)((lane >> 4) << 3);
    uint32_t bRow = (uint32_t)((lane & 7) + ((lane >> 4) << 3));
    uint32_t bKof = (uint32_t)(((lane >> 3) & 1) << 3);
    int grp = lane >> 2, tix = lane & 3;

    // ---- phase 0: load G, W1, Wout (fp32 -> bf16 hi/lo), s, biases ----
    for (int idx = tid*4; idx < 16384; idx += 1024) {
        int r = idx >> 7, c = idx & 127;
        float4 g = *(const float4*)(Gsrc + idx);
        __nv_bfloat16 h0 = __float2bfloat16(g.x), h1 = __float2bfloat16(g.y),
                      h2 = __float2bfloat16(g.z), h3 = __float2bfloat16(g.w);
        *(uint2*)(sGh + r*136 + c) = make_uint2(bfp(h0, h1), bfp(h2, h3));
        *(uint2*)(sGl + r*136 + c) = make_uint2(
            bfp2(g.x - __bfloat162float(h0), g.y - __bfloat162float(h1)),
            bfp2(g.z - __bfloat162float(h2), g.w - __bfloat162float(h3)));
        float4 w = *(const float4*)(W1 + idx);
        h0 = __float2bfloat16(w.x); h1 = __float2bfloat16(w.y);
        h2 = __float2bfloat16(w.z); h3 = __float2bfloat16(w.w);
        *(uint2*)(sT1h + r*136 + c) = make_uint2(bfp(h0, h1), bfp(h2, h3));
        *(uint2*)(sT1l + r*136 + c) = make_uint2(
            bfp2(w.x - __bfloat162float(h0), w.y - __bfloat162float(h1)),
            bfp2(w.z - __bfloat162float(h2), w.w - __bfloat162float(h3)));
        float4 wo = *(const float4*)(Wout + idx);
        h0 = __float2bfloat16(wo.x); h1 = __float2bfloat16(wo.y);
        h2 = __float2bfloat16(wo.z); h3 = __float2bfloat16(wo.w);
        *(uint2*)(sWoh + r*136 + c) = make_uint2(bfp(h0, h1), bfp(h2, h3));
        *(uint2*)(sWol + r*136 + c) = make_uint2(
            bfp2(wo.x - __bfloat162float(h0), wo.y - __bfloat162float(h1)),
            bfp2(wo.z - __bfloat162float(h2), wo.w - __bfloat162float(h3)));
    }
    if (tid < 128) { sS[tid] = dS[(s*NT + t)*Cc + tid]; sb1[tid] = B1[tid]; }
    if (tid < 64)  sb2[tid] = B2[tid];
    __syncthreads();

    // ---- GEMM1: T1 = W1 @ G  (A = W1 [o][c], B = G [l][c] via symmetry) ----
    int m0 = (wid & 3)*32, n0 = (wid >> 2)*64;
    float accT[2][8][4];
    #pragma unroll
    for (int a = 0; a < 2; a++)
        #pragma unroll
        for (int nt = 0; nt < 8; nt++)
            #pragma unroll
            for (int e = 0; e < 4; e++) accT[a][nt][e] = 0.f;

    #pragma unroll 2
    for (int ks = 0; ks < 8; ks++) {
        uint32_t k0 = (uint32_t)(ks*16);
        uint32_t ahi[2][4], alo[2][4], bhi[8][2], blo[8][2];
        #pragma unroll
        for (int a = 0; a < 2; a++) {
            uint32_t eo = ((uint32_t)(m0 + a*16) + aRow)*136u + k0 + aKof;
            ldm4(ahi[a], uT1h + eo*2u);   // W1 currently lives here
            ldm4(alo[a], uT1l + eo*2u);
        }
        #pragma unroll
        for (int p = 0; p < 4; p++) {
            uint32_t eo = ((uint32_t)(n0 + p*16) + bRow)*136u + k0 + bKof;
            uint32_t r[4];
            ldm4(r, uGh + eo*2u);
            bhi[2*p][0] = r[0]; bhi[2*p][1] = r[1];
            bhi[2*p+1][0] = r[2]; bhi[2*p+1][1] = r[3];
            ldm4(r, uGl + eo*2u);
            blo[2*p][0] = r[0]; blo[2*p][1] = r[1];
            blo[2*p+1][0] = r[2]; blo[2*p+1][1] = r[3];
        }
        #pragma unroll
        for (int a = 0; a < 2; a++)
            #pragma unroll
            for (int nt = 0; nt < 8; nt++) {
                mma16816(accT[a][nt], ahi[a], bhi[nt]);
                mma16816(accT[a][nt], ahi[a], blo[nt]);
                mma16816(accT[a][nt], alo[a], bhi[nt]);
            }
    }
    __syncthreads();   // GEMM1 done: G region free

    // ---- phase: load W2 into R1; w1s from W1 (still intact in R2) ----
    for (int idx = tid*4; idx < 8192; idx += 1024) {
        int r = idx >> 7, c = idx & 127;
        float4 w = *(const float4*)(W2 + idx);
        __nv_bfloat16 h0 = __float2bfloat16(w.x), h1 = __float2bfloat16(w.y),
                      h2 = __float2bfloat16(w.z), h3 = __float2bfloat16(w.w);
        *(uint2*)(sW2h + r*136 + c) = make_uint2(bfp(h0, h1), bfp(h2, h3));
        *(uint2*)(sW2l + r*136 + c) = make_uint2(
            bfp2(w.x - __bfloat162float(h0), w.y - __bfloat162float(h1)),
            bfp2(w.z - __bfloat162float(h2), w.w - __bfloat162float(h3)));
    }
    if (tid < 128) {   // w1s = W1 s  (reconstruct from hi+lo)
        float a = 0.f;
        for (int c = 0; c < 128; c++) {
            float w = __bfloat162float(__ushort_as_bfloat16(sT1h[tid*136 + c]))
                    + __bfloat162float(__ushort_as_bfloat16(sT1l[tid*136 + c]));
            a = fmaf(w, sS[c], a);
        }
        w1s[tid] = a;
    }
    __syncthreads();

    // ---- write T1 hi/lo into R2 (W1 dead); w2s from W2 ----
    #pragma unroll
    for (int a = 0; a < 2; a++)
        #pragma unroll
        for (int nt = 0; nt < 8; nt++) {
            int r0 = m0 + a*16 + grp, cc = n0 + nt*8 + tix*2;
            float e0 = accT[a][nt][0], e1 = accT[a][nt][1];
            float e2 = accT[a][nt][2], e3 = accT[a][nt][3];
            __nv_bfloat16 h0 = __float2bfloat16(e0), h1 = __float2bfloat16(e1);
            __nv_bfloat16 h2 = __float2bfloat16(e2), h3 = __float2bfloat16(e3);
            *(uint32_t*)(sT1h + r0*136 + cc)     = bfp(h0, h1);
            *(uint32_t*)(sT1h + (r0+8)*136 + cc) = bfp(h2, h3);
            *(uint32_t*)(sT1l + r0*136 + cc)     = bfp2(e0 - __bfloat162float(h0), e1 - __bfloat162float(h1));
            *(uint32_t*)(sT1l + (r0+8)*136 + cc) = bfp2(e2 - __bfloat162float(h2), e3 - __bfloat162float(h3));
        }
    if (tid < 64) {    // w2s = W2 s
        float a = 0.f;
        for (int c = 0; c < 128; c++) {
            float w = __bfloat162float(__ushort_as_bfloat16(sW2h[tid*136 + c]))
                    + __bfloat162float(__ushort_as_bfloat16(sW2l[tid*136 + c]));
            a = fmaf(w, sS[c], a);
        }
        w2s[tid] = a;
    }
    __syncthreads();

    // ---- GEMM2: M = T1 @ W2^T   (A = T1 [i][c], B = W2 [k][c]) ----
    int m2 = (wid & 3)*32, n2 = (wid >> 2)*32;
    {
        float accM[2][4][4];
        #pragma unroll
        for (int a = 0; a < 2; a++)
            #pragma unroll
            for (int nt = 0; nt < 4; nt++)
                #pragma unroll
                for (int e = 0; e < 4; e++) accM[a][nt][e] = 0.f;

        #pragma unroll 2
        for (int ks = 0; ks < 8; ks++) {
            uint32_t k0 = (uint32_t)(ks*16);
            uint32_t ahi[2][4], alo[2][4], bhi[4][2], blo[4][2];
            #pragma unroll
            for (int a = 0; a < 2; a++) {
                uint32_t eo = ((uint32_t)(m2 + a*16) + aRow)*136u + k0 + aKof;
                ldm4(ahi[a], uT1h + eo*2u);
                ldm4(alo[a], uT1l + eo*2u);
            }
            #pragma unroll
            for (int p = 0; p < 2; p++) {
                uint32_t eo = ((uint32_t)(n2 + p*16) + bRow)*136u + k0 + bKof;
                uint32_t r[4];
                ldm4(r, uW2h + eo*2u);
                bhi[2*p][0] = r[0]; bhi[2*p][1] = r[1];
                bhi[2*p+1][0] = r[2]; bhi[2*p+1][1] = r[3];
                ldm4(r, uW2l + eo*2u);
                blo[2*p][0] = r[0]; blo[2*p][1] = r[1];
                blo[2*p+1][0] = r[2]; blo[2*p+1][1] = r[3];
            }
            #pragma unroll
            for (int a = 0; a < 2; a++)
                #pragma unroll
                for (int nt = 0; nt < 4; nt++) {
                    mma16816(accM[a][nt], ahi[a], bhi[nt]);
                    mma16816(accM[a][nt], ahi[a], blo[nt]);
                    mma16816(accM[a][nt], alo[a], bhi[nt]);
                }
        }

        // store M + rank-1 bias terms (fp32)
        #pragma unroll
        for (int a = 0; a < 2; a++)
            #pragma unroll
            for (int nt = 0; nt < 4; nt++) {
                int i0 = m2 + a*16 + grp, kk = n2 + nt*8 + tix*2;
                float b1lo = sb1[i0], b1hi = sb1[i0 + 8];
                float b2a = sb2[kk], b2b = sb2[kk + 1];
                sM[i0*68 + kk]     = accM[a][nt][0] + w1s[i0]*b2a   + b1lo*w2s[kk]   + 1024.f*b1lo*b2a;
                sM[i0*68 + kk + 1] = accM[a][nt][1] + w1s[i0]*b2b   + b1lo*w2s[kk+1] + 1024.f*b1lo*b2b;
                sM[(i0+8)*68 + kk]     = accM[a][nt][2] + w1s[i0+8]*b2a + b1hi*w2s[kk]   + 1024.f*b1hi*b2a;
                sM[(i0+8)*68 + kk + 1] = accM[a][nt][3] + w1s[i0+8]*b2b + b1hi*w2s[kk+1] + 1024.f*b1hi*b2b;
            }
    }
    __syncthreads();

    // ---- column L2 norms over i ----
    if (tid < 64) {
        float ss = 0.f;
        for (int i = 0; i < 128; i++) { float v = sM[i*68 + tid]; ss = fmaf(v, v, ss); }
        nk[tid] = 1.f / (1e-6f + sqrtf(ss));
    }
    __syncthreads();

    // ---- u^T hi/lo into R2 (T1 dead) ----
    for (int idx = tid; idx < 8192; idx += 256) {
        int i = idx & 127, k = idx >> 7;
        float v = sM[i*68 + k] * nk[k];
        __nv_bfloat16 h = __float2bfloat16(v);
        sUh[k*136 + i] = __bfloat16_as_ushort(h);
        sUl[k*136 + i] = __bfloat16_as_ushort(__float2bfloat16(v - __bfloat162float(h)));
    }
    __syncthreads();

    // ---- GEMM3: A = Wout @ u   (A = Wout [o][i], B = u^T [k][i]) ----
    {
        float accA[2][4][4];
        #pragma unroll
        for (int a = 0; a < 2; a++)
            #pragma unroll
            for (int nt = 0; nt < 4; nt++)
                #pragma unroll
                for (int e = 0; e < 4; e++) accA[a][nt][e] = 0.f;

        #pragma unroll 2
        for (int ks = 0; ks < 8; ks++) {
            uint32_t k0 = (uint32_t)(ks*16);
            uint32_t ahi[2][4], alo[2][4], bhi[4][2], blo[4][2];
            #pragma unroll
            for (int a = 0; a < 2; a++) {
                uint32_t eo = ((uint32_t)(m2 + a*16) + aRow)*136u + k0 + aKof;
                ldm4(ahi[a], uWoh + eo*2u);
                ldm4(alo[a], uWol + eo*2u);
            }
            #pragma unroll
            for (int p = 0; p < 2; p++) {
                uint32_t eo = ((uint32_t)(n2 + p*16) + bRow)*136u + k0 + bKof;
                uint32_t r[4];
                ldm4(r, uUh + eo*2u);
                bhi[2*p][0] = r[0]; bhi[2*p][1] = r[1];
                bhi[2*p+1][0] = r[2]; bhi[2*p+1][1] = r[3];
                ldm4(r, uUl + eo*2u);
                blo[2*p][0] = r[0]; blo[2*p][1] = r[1];
                blo[2*p+1][0] = r[2]; blo[2*p+1][1] = r[3];
            }
            #pragma unroll
            for (int a = 0; a < 2; a++)
                #pragma unroll
                for (int nt = 0; nt < 4; nt++) {
                    mma16816(accA[a][nt], ahi[a], bhi[nt]);
                    mma16816(accA[a][nt], ahi[a], blo[nt]);
                    mma16816(accA[a][nt], alo[a], bhi[nt]);
                }
        }

        ush* AH = dAh + ((long)(s*NT + t) << 13);
        ush* AL = dAl + ((long)(s*NT + t) << 13);
        #pragma unroll
        for (int a = 0; a < 2; a++)
            #pragma unroll
            for (int nt = 0; nt < 4; nt++) {
                int o = m2 + a*16 + grp, kk = n2 + nt*8 + tix*2;
                float e0 = accA[a][nt][0], e1 = accA[a][nt][1];
                float e2 = accA[a][nt][2], e3 = accA[a][nt][3];
                __nv_bfloat16 h0 = __float2bfloat16(e0), h1 = __float2bfloat16(e1);
                __nv_bfloat16 h2 = __float2bfloat16(e2), h3 = __float2bfloat16(e3);
                *(uint32_t*)(AH + o*64 + kk)     = bfp(h0, h1);
                *(uint32_t*)(AH + (o+8)*64 + kk) = bfp(h2, h3);
                *(uint32_t*)(AL + o*64 + kk)     = bfp2(e0 - __bfloat162float(h0), e1 - __bfloat162float(h1));
                *(uint32_t*)(AL + (o+8)*64 + kk) = bfp2(e2 - __bfloat162float(h2), e3 - __bfloat162float(h3));
            }
    }
}

// ---------------------------------------------------------------------------
// Kernel C (HMMA v3): single-phase V GEMM + register softmax; A-hi in regs,
// A-lo from smem. (unchanged from R11)
// ---------------------------------------------------------------------------
__global__ __launch_bounds__(256) void out_kernel(const float* __restrict__ x1,
                                                  const float* __restrict__ x2,
                                                  const float* __restrict__ Wv,
                                                  const float* __restrict__ bv,
                                                  float* __restrict__ out1,
                                                  float* __restrict__ out2)
{
    extern __shared__ char osm[];
    ush*   sWvH = (ush*)osm;                    // [64][264]
    ush*   sWvL = (ush*)(osm + 33792);
    ush*   sXH  = (ush*)(osm + 67584);          // [256][72]
    ush*   sXL  = (ush*)(osm + 104448);
    ush*   sALo = (ush*)(osm + 141312);         // [2][128][72]
    ush*   sVH  = (ush*)(osm + 178176);         // [64][72]
    ush*   sVL  = (ush*)(osm + 187392);
    float* redM = (float*)(osm + 196608);       // [4][64]
    float* redS = (float*)(osm + 197632);
    float* sbv  = (float*)(osm + 198656);

    uint32_t uWvH = s2u(sWvH), uWvL = s2u(sWvL);
    uint32_t uXH = s2u(sXH), uXL = s2u(sXL);
    uint32_t uALo = s2u(sALo);
    uint32_t uVH = s2u(sVH), uVL = s2u(sVL);

    int t = blockIdx.x, halfy = blockIdx.y;
    int b  = t >> 6, q = t & 63;
    int pi = q >> 3, pj = q & 7;
    long base0 = (long)b*Cc*HW + (long)(pi*32)*Ww + pj*32;
    int li0 = halfy*16;

    int tid = threadIdx.x, wid = tid >> 5, lane = tid & 31;
    int c0 = tid >> 1, h2 = tid & 1;
    const float* x1base = x1 + base0 + (long)c0*HW;
    const float* x2base = x2 + base0 + (long)c0*HW;
    uint32_t xo1 = ((uint32_t)c0*72u + (uint32_t)h2*32u)*2u;
    uint32_t xo2 = (((uint32_t)(128 + c0))*72u + (uint32_t)h2*32u)*2u;

    float4 p1[8], p2[8];
    {
        const float4* s1 = (const float4*)(x1base + (long)(li0 + h2)*Ww);
        const float4* s2 = (const float4*)(x2base + (long)(li0 + h2)*Ww);
        #pragma unroll
        for (int j = 0; j < 8; j++) { p1[j] = s1[j]; p2[j] = s2[j]; }
    }

    for (int idx = tid; idx < 16384; idx += 256) {
        int r = idx >> 8, c = idx & 255;
        float v = Wv[idx];
        __nv_bfloat16 h = __float2bfloat16(v);
        sWvH[r*264 + c] = __bfloat16_as_ushort(h);
        sWvL[r*264 + c] = __bfloat16_as_ushort(__float2bfloat16(v - __bfloat162float(h)));
    }
    for (int idx = tid; idx < 16384; idx += 256) {
        int s_ = idx >> 13, rem = idx & 8191;
        int o = rem >> 6, k = rem & 63;
        long gsrc = ((long)(s_*NT + t) << 13) + rem;
        sXH[(s_*128 + o)*72 + k]  = dAh[gsrc];
        sALo[(s_*128 + o)*72 + k] = dAl[gsrc];
    }
    if (tid < 64) sbv[tid] = bv[tid];
    __syncthreads();

    uint32_t aRow = (uint32_t)(lane & 15);
    uint32_t aKof = (uint32_t)((lane >> 4) << 3);
    uint32_t g = (uint32_t)(lane >> 3), rr8 = (uint32_t)(lane & 7);
    uint32_t tKrow = ((g & 1u) << 3) + rr8;
    uint32_t tNcol = (g >> 1) << 3;
    int grp = lane >> 2, tix = lane & 3;

    int vm0 = (wid & 3)*16, vn0 = (wid >> 2)*32;
    int st = wid >> 2, om0 = (wid & 3)*32;
    float* outp = st ? out2 : out1;
    uint32_t aBase = ((uint32_t)(st*128 + om0) + aRow)*72u + aKof;

    uint32_t aAh[2][4][4];
    #pragma unroll
    for (int a = 0; a < 2; a++)
        #pragma unroll
        for (int ks = 0; ks < 4; ks++) {
            uint32_t ao = aBase + (uint32_t)(a*16)*72u + (uint32_t)(ks*16);
            ldm4(aAh[a][ks], uXH + ao*2u);
        }
    __syncthreads();

    #pragma unroll
    for (int j = 0; j < 8; j++) {
        float4 v = p1[j];
        __nv_bfloat16 hx = __float2bfloat16(v.x), hy = __float2bfloat16(v.y),
                      hz = __float2bfloat16(v.z), hw = __float2bfloat16(v.w);
        uint32_t off = xo1 + 8u*j;
        *(uint2*)((char*)sXH + off) = make_uint2(bfp(hx, hy), bfp(hz, hw));
        *(uint2*)((char*)sXL + off) = make_uint2(
            bfp2(v.x - __bfloat162float(hx), v.y - __bfloat162float(hy)),
            bfp2(v.z - __bfloat162float(hz), v.w - __bfloat162float(hw)));
        v = p2[j];
        hx = __float2bfloat16(v.x); hy = __float2bfloat16(v.y);
        hz = __float2bfloat16(v.z); hw = __float2bfloat16(v.w);
        off = xo2 + 8u*j;
        *(uint2*)((char*)sXH + off) = make_uint2(bfp(hx, hy), bfp(hz, hw));
        *(uint2*)((char*)sXL + off) = make_uint2(
            bfp2(v.x - __bfloat162float(hx), v.y - __bfloat162float(hy)),
            bfp2(v.z - __bfloat162float(hz), v.w - __bfloat162float(hw)));
    }
    __syncthreads();

    for (int ch = 0; ch < 8; ch++) {
        int lrow = li0 + 2*ch;

        if (ch < 7) {
            const float4* s1 = (const float4*)(x1base + (long)(lrow + 2 + h2)*Ww);
            const float4* s2 = (const float4*)(x2base + (long)(lrow + 2 + h2)*Ww);
            #pragma unroll
            for (int j = 0; j < 8; j++) { p1[j] = s1[j]; p2[j] = s2[j]; }
        }

        float accV[4][4];
        #pragma unroll
        for (int nt = 0; nt < 4; nt++)
            #pragma unroll
            for (int e = 0; e < 4; e++) accV[nt][e] = 0.f;

        #pragma unroll 2
        for (int ks = 0; ks < 16; ks++) {
            uint32_t kx = (uint32_t)(ks*16);
            uint32_t ah[4], al[4], bh[8], bl[8];
            uint32_t ao = ((uint32_t)vm0 + aRow)*264u + kx + aKof;
            ldm4(ah, uWvH + ao*2u);
            ldm4(al, uWvL + ao*2u);
            uint32_t bo0 = (kx + tKrow)*72u + (uint32_t)vn0 + tNcol;
            ldm4t(bh,     uXH + bo0*2u);
            ldm4t(bh + 4, uXH + (bo0 + 16u)*2u);
            ldm4t(bl,     uXL + bo0*2u);
            ldm4t(bl + 4, uXL + (bo0 + 16u)*2u);
            #pragma unroll
            for (int nt = 0; nt < 4; nt++) {
                mma16816(accV[nt], ah, bh + 2*nt);
                mma16816(accV[nt], ah, bl + 2*nt);
                mma16816(accV[nt], al, bh + 2*nt);
            }
        }

        float ev[4][4];
        float bvlo = sbv[vm0 + grp], bvhi = sbv[vm0 + grp + 8];
        float mx[4][2];
        #pragma unroll
        for (int nt = 0; nt < 4; nt++) {
            ev[nt][0] = accV[nt][0] + bvlo;
            ev[nt][1] = accV[nt][1] + bvlo;
            ev[nt][2] = accV[nt][2] + bvhi;
            ev[nt][3] = accV[nt][3] + bvhi;
            mx[nt][0] = fmaxf(ev[nt][0], ev[nt][2]);
            mx[nt][1] = fmaxf(ev[nt][1], ev[nt][3]);
        }
        #pragma unroll
        for (int o = 4; o <= 16; o <<= 1)
            #pragma unroll
            for (int nt = 0; nt < 4; nt++) {
                mx[nt][0] = fmaxf(mx[nt][0], __shfl_xor_sync(0xffffffffu, mx[nt][0], o));
                mx[nt][1] = fmaxf(mx[nt][1], __shfl_xor_sync(0xffffffffu, mx[nt][1], o));
            }
        if (grp == 0) {
            #pragma unroll
            for (int nt = 0; nt < 4; nt++) {
                int c = vn0 + nt*8 + tix*2;
                redM[(wid & 3)*64 + c]     = mx[nt][0];
                redM[(wid & 3)*64 + c + 1] = mx[nt][1];
            }
        }
        __syncthreads();

        if (ch < 7) {
            #pragma unroll
            for (int j = 0; j < 8; j++) {
                float4 v = p1[j];
                __nv_bfloat16 hx = __float2bfloat16(v.x), hy = __float2bfloat16(v.y),
                              hz = __float2bfloat16(v.z), hw = __float2bfloat16(v.w);
                uint32_t off = xo1 + 8u*j;
                *(uint2*)((char*)sXH + off) = make_uint2(bfp(hx, hy), bfp(hz, hw));
                *(uint2*)((char*)sXL + off) = make_uint2(
                    bfp2(v.x - __bfloat162float(hx), v.y - __bfloat162float(hy)),
                    bfp2(v.z - __bfloat162float(hz), v.w - __bfloat162float(hw)));
                v = p2[j];
                hx = __float2bfloat16(v.x); hy = __float2bfloat16(v.y);
                hz = __float2bfloat16(v.z); hw = __float2bfloat16(v.w);
                off = xo2 + 8u*j;
                *(uint2*)((char*)sXH + off) = make_uint2(bfp(hx, hy), bfp(hz, hw));
                *(uint2*)((char*)sXL + off) = make_uint2(
                    bfp2(v.x - __bfloat162float(hx), v.y - __bfloat162float(hy)),
                    bfp2(v.z - __bfloat162float(hz), v.w - __bfloat162float(hw)));
            }
        }

        float sm0[4][2];
        #pragma unroll
        for (int nt = 0; nt < 4; nt++) {
            int c = vn0 + nt*8 + tix*2;
            float m0 = fmaxf(fmaxf(redM[c], redM[64 + c]), fmaxf(redM[128 + c], redM[192 + c]));
            float m1 = fmaxf(fmaxf(redM[c+1], redM[64 + c+1]), fmaxf(redM[128 + c+1], redM[192 + c+1]));
            ev[nt][0] = __expf(ev[nt][0] - m0);
            ev[nt][1] = __expf(ev[nt][1] - m1);
            ev[nt][2] = __expf(ev[nt][2] - m0);
            ev[nt][3] = __expf(ev[nt][3] - m1);
            sm0[nt][0] = ev[nt][0] + ev[nt][2];
            sm0[nt][1] = ev[nt][1] + ev[nt][3];
        }
        #pragma unroll
        for (int o = 4; o <= 16; o <<= 1)
            #pragma unroll
            for (int nt = 0; nt < 4; nt++) {
                sm0[nt][0] += __shfl_xor_sync(0xffffffffu, sm0[nt][0], o);
                sm0[nt][1] += __shfl_xor_sync(0xffffffffu, sm0[nt][1], o);
            }
        if (grp == 0) {
            #pragma unroll
            for (int nt = 0; nt < 4; nt++) {
                int c = vn0 + nt*8 + tix*2;
                redS[(wid & 3)*64 + c]     = sm0[nt][0];
                redS[(wid & 3)*64 + c + 1] = sm0[nt][1];
            }
        }
        __syncthreads();

        #pragma unroll
        for (int nt = 0; nt < 4; nt++) {
            int c = vn0 + nt*8 + tix*2;
            float i0 = 1.f / (redS[c] + redS[64 + c] + redS[128 + c] + redS[192 + c]);
            float i1 = 1.f / (redS[c+1] + redS[64 + c+1] + redS[128 + c+1] + redS[192 + c+1]);
            float v0 = ev[nt][0]*i0, v1 = ev[nt][1]*i1, v2 = ev[nt][2]*i0, v3 = ev[nt][3]*i1;
            __nv_bfloat16 h0 = __float2bfloat16(v0), h1 = __float2bfloat16(v1),
                          h2b = __float2bfloat16(v2), h3 = __float2bfloat16(v3);
            int r0 = vm0 + grp;
            *(uint32_t*)(sVH + r0*72 + c)     = bfp(h0, h1);
            *(uint32_t*)(sVH + (r0+8)*72 + c) = bfp(h2b, h3);
            *(uint32_t*)(sVL + r0*72 + c)     = bfp2(v0 - __bfloat162float(h0), v1 - __bfloat162float(h1));
            *(uint32_t*)(sVL + (r0+8)*72 + c) = bfp2(v2 - __bfloat162float(h2b), v3 - __bfloat162float(h3));
        }
        __syncthreads();

        {
            float accO[2][8][4];
            #pragma unroll
            for (int a = 0; a < 2; a++)
                #pragma unroll
                for (int nt = 0; nt < 8; nt++)
                    #pragma unroll
                    for (int e = 0; e < 4; e++) accO[a][nt][e] = 0.f;

            #pragma unroll
            for (int ks = 0; ks < 4; ks++) {
                uint32_t k0 = (uint32_t)(ks*16);
                uint32_t bh[16], bl[16], aal[2][4];
                #pragma unroll
                for (int qq = 0; qq < 4; qq++) {
                    uint32_t bo = (k0 + tKrow)*72u + (uint32_t)(qq*16) + tNcol;
                    ldm4t(bh + 4*qq, uVH + bo*2u);
                    ldm4t(bl + 4*qq, uVL + bo*2u);
                }
                #pragma unroll
                for (int a = 0; a < 2; a++) {
                    uint32_t ao = aBase + (uint32_t)(a*16)*72u + k0;
                    ldm4(aal[a], uALo + ao*2u);
                }
                #pragma unroll
                for (int a = 0; a < 2; a++)
                    #pragma unroll
                    for (int nt = 0; nt < 8; nt++) {
                        const uint32_t* ph = bh + 4*(nt >> 1) + 2*(nt & 1);
                        const uint32_t* pl = bl + 4*(nt >> 1) + 2*(nt & 1);
                        mma16816(accO[a][nt], aAh[a][ks], ph);
                        mma16816(accO[a][nt], aAh[a][ks], pl);
                        mma16816(accO[a][nt], aal[a], ph);
                    }
            }

            #pragma unroll
            for (int a = 0; a < 2; a++)
                #pragma unroll
                for (int nt = 0; nt < 8; nt++) {
                    int o = om0 + a*16 + grp;
                    int l = nt*8 + tix*2;
                    int lr = l >> 5, lj = l & 31;
                    long gaddr = ((long)(b*Cc + o)*Hh + (pi*32 + lrow + lr))*Ww + pj*32 + lj;
                    float2 v0; v0.x = accO[a][nt][0]; v0.y = accO[a][nt][1];
                    float2 v1; v1.x = accO[a][nt][2]; v1.y = accO[a][nt][3];
                    *(float2*)(outp + gaddr)         = v0;
                    *(float2*)(outp + gaddr + 8l*HW) = v1;
                }
        }
        __syncthreads();
    }
}

extern "C" void kernel_launch(void* const* d_in, const int* in_sizes, int n_in,
                              void* d_out, int out_size)
{
    const float* x1     = (const float*)d_in[0];
    const float* x2     = (const float*)d_in[1];
    const float* w_v    = (const float*)d_in[2];
    const float* b_v    = (const float*)d_in[3];
    const float* w1_1   = (const float*)d_in[4];
    const float* b1_1   = (const float*)d_in[5];
    const float* w2_1   = (const float*)d_in[6];
    const float* b2_1   = (const float*)d_in[7];
    const float* w_out1 = (const float*)d_in[8];
    const float* w1_2   = (const float*)d_in[9];
    const float* b1_2   = (const float*)d_in[10];
    const float* w2_2   = (const float*)d_in[11];
    const float* b2_2   = (const float*)d_in[12];
    const float* w_out2 = (const float*)d_in[13];
    (void)in_sizes; (void)n_in; (void)out_size;

    float* out1 = (float*)d_out;
    float* out2 = out1 + (size_t)Bb*Cc*HW;

    cudaFuncSetAttribute(gram_kernel, cudaFuncAttributeMaxDynamicSharedMemorySize, GRAM2_SMEM);
    cudaFuncSetAttribute(mid_kernel, cudaFuncAttributeMaxDynamicSharedMemorySize, MID2_SMEM);
    cudaFuncSetAttribute(out_kernel, cudaFuncAttributeMaxDynamicSharedMemorySize, OUT3_SMEM);

    gram_kernel<<<dim3(NT, 2), 256, GRAM2_SMEM>>>(x1, x2);
    mid_kernel<<<dim3(NT, 2), 256, MID2_SMEM>>>(w1_1, b1_1, w2_1, b2_1, w_out1,
                                                w1_2, b1_2, w2_2, b2_2, w_out2);
    out_kernel<<<dim3(NT, 2), 256, OUT3_SMEM>>>(x1, x2, w_v, b_v, out1, out2);
}

// round 13
// speedup vs baseline: 1.4012x; 1.4012x over previous
#include <cuda_runtime.h>
#include <cuda_bf16.h>
#include <math.h>
#include <stdint.h>

#define Bb 4
#define Cc 128
#define Kk 64
#define Hh 256
#define Ww 256
#define HW (Hh*Ww)
#define NT 256          // B * P*P tiles
#define MID_SMEM_FLOATS 51072
#define MID_SMEM (MID_SMEM_FLOATS*4)
#define LDB 72          // bf16 elements per smem row (64 data + 8 pad)
#define GRAM2_SMEM 73728
#define OUT2_SMEM 215296

typedef unsigned short ush;

// ---- packed fp32x2 helpers (FFMA2) ----
typedef unsigned long long u64t;
__device__ __forceinline__ u64t f2pack(float lo, float hi){
    u64t r; asm("mov.b64 %0, {%1,%2};" : "=l"(r) : "f"(lo), "f"(hi)); return r;
}
__device__ __forceinline__ u64t f2splat(float v){ return f2pack(v, v); }
__device__ __forceinline__ void f2unpack(u64t v, float& lo, float& hi){
    asm("mov.b64 {%0,%1}, %2;" : "=f"(lo), "=f"(hi) : "l"(v));
}
__device__ __forceinline__ void f2fma(u64t& d, u64t a, u64t b){
    asm("fma.rn.f32x2 %0, %1, %2, %3;" : "=l"(d) : "l"(a), "l"(b), "l"(d));
}

// ---- mma.sync helpers (arch-neutral tensor path) ----
__device__ __forceinline__ uint32_t s2u(const void* p){
    uint32_t a;
    asm("{ .reg .u64 t; cvta.to.shared.u64 t, %1; cvt.u32.u64 %0, t; }" : "=r"(a) : "l"(p));
    return a;
}
__device__ __forceinline__ void ldm4(uint32_t* d, uint32_t addr){
    asm volatile("ldmatrix.sync.aligned.m8n8.x4.shared.b16 {%0,%1,%2,%3}, [%4];"
        : "=r"(d[0]), "=r"(d[1]), "=r"(d[2]), "=r"(d[3]) : "r"(addr));
}
__device__ __forceinline__ void ldm4t(uint32_t* d, uint32_t addr){
    asm volatile("ldmatrix.sync.aligned.m8n8.x4.trans.shared.b16 {%0,%1,%2,%3}, [%4];"
        : "=r"(d[0]), "=r"(d[1]), "=r"(d[2]), "=r"(d[3]) : "r"(addr));
}
__device__ __forceinline__ void mma16816(float* c, const uint32_t* a, const uint32_t* b){
    asm volatile("mma.sync.aligned.m16n8k16.row.col.f32.bf16.bf16.f32 "
        "{%0,%1,%2,%3}, {%4,%5,%6,%7}, {%8,%9}, {%0,%1,%2,%3};"
        : "+f"(c[0]), "+f"(c[1]), "+f"(c[2]), "+f"(c[3])
        : "r"(a[0]), "r"(a[1]), "r"(a[2]), "r"(a[3]), "r"(b[0]), "r"(b[1]));
}
__device__ __forceinline__ uint32_t bfp(__nv_bfloat16 a, __nv_bfloat16 b){
    return ((uint32_t)__bfloat16_as_ushort(b) << 16) | (uint32_t)__bfloat16_as_ushort(a);
}
__device__ __forceinline__ uint32_t bfp2(float a, float b){
    return bfp(__float2bfloat16(a), __float2bfloat16(b));
}

// Scratch (allocation-free rule: __device__ globals)
__device__ float dG[2*NT*Cc*Cc];   // per (stream,tile) Gram 128x128
__device__ float dS[2*NT*Cc];      // per (stream,tile) row sums
__device__ ush   dAh[2*NT*Cc*Kk];  // A hi bf16, layout [s][t][o=128][k=64]
__device__ ush   dAl[2*NT*Cc*Kk];  // A lo bf16

// ---------------------------------------------------------------------------
// Kernel A (HMMA, R10 version): G = X X^T with symmetric 2-product split:
//   G = HH + Q + Q^T,  HH = Xhi Xhi^T,  Q = Xhi Xlo^T  (lo on B side).
// Double-buffered smem tiles; ONE sync per chunk. Q^T assembled via smem.
// ---------------------------------------------------------------------------
__global__ __launch_bounds__(256) void gram_kernel(const float* __restrict__ x1,
                                                   const float* __restrict__ x2)
{
    extern __shared__ char gsm[];
    uint32_t gb = s2u(gsm);

    int t = blockIdx.x, s = blockIdx.y;
    const float* x = s ? x2 : x1;
    int b = t >> 6, q = t & 63;
    int pi = q >> 3, pj = q & 7;
    long base0 = (long)b*Cc*HW + (long)(pi*32)*Ww + pj*32;

    int tid = threadIdx.x, wid = tid >> 5, lane = tid & 31;
    int c0 = tid >> 1, half = tid & 1;
    const float* rowbase = x + base0 + (long)c0*HW + (long)half*Ww;

    int wm = wid & 3, wn = wid >> 2;
    int m0 = wm*32, n0 = wn*64;

    float acc_hh[2][8][4], acc_q[2][8][4];
    #pragma unroll
    for (int a = 0; a < 2; a++)
        #pragma unroll
        for (int nt = 0; nt < 8; nt++)
            #pragma unroll
            for (int e = 0; e < 4; e++) { acc_hh[a][nt][e] = 0.f; acc_q[a][nt][e] = 0.f; }

    float ps = 0.f;
    float4 pref[8];
    {
        const float4* src = (const float4*)rowbase;
        #pragma unroll
        for (int j = 0; j < 8; j++) pref[j] = src[j];
    }

    uint32_t aRow = (uint32_t)(lane & 15);
    uint32_t aKof = (uint32_t)((lane >> 4) << 3);
    uint32_t bRow = (uint32_t)((lane & 7) + ((lane >> 4) << 3));
    uint32_t bKof = (uint32_t)(((lane >> 3) & 1) << 3);

    uint32_t wo = ((uint32_t)c0*LDB + (uint32_t)half*32u)*2u;

    #pragma unroll
    for (int j = 0; j < 8; j++) {
        float4 v = pref[j];
        ps += (v.x + v.y) + (v.z + v.w);
        __nv_bfloat16 hx = __float2bfloat16(v.x), hy = __float2bfloat16(v.y),
                      hz = __float2bfloat16(v.z), hw = __float2bfloat16(v.w);
        uint32_t off = wo + 8u*j;
        *(uint2*)(gsm + off) = make_uint2(bfp(hx, hy), bfp(hz, hw));
        *(uint2*)(gsm + 18432 + off) = make_uint2(
            bfp2(v.x - __bfloat162float(hx), v.y - __bfloat162float(hy)),
            bfp2(v.z - __bfloat162float(hz), v.w - __bfloat162float(hw)));
    }
    {
        const float4* src = (const float4*)(rowbase + (long)2*Ww);
        #pragma unroll
        for (int j = 0; j < 8; j++) pref[j] = src[j];
    }
    __syncthreads();

    for (int ch = 0; ch < 16; ch++) {
        uint32_t hiB = gb + (uint32_t)(ch & 1)*36864u;
        uint32_t loB = hiB + 18432u;

        #pragma unroll
        for (int ks = 0; ks < 4; ks++) {
            uint32_t k0 = (uint32_t)(ks*16);
            uint32_t ahi[2][4], bhi[8][2], blo[8][2];
            #pragma unroll
            for (int a = 0; a < 2; a++) {
                uint32_t eo = ((uint32_t)(m0 + a*16) + aRow)*LDB + k0 + aKof;
                ldm4(ahi[a], hiB + eo*2u);
            }
            #pragma unroll
            for (int p = 0; p < 4; p++) {
                uint32_t eo = ((uint32_t)(n0 + p*16) + bRow)*LDB + k0 + bKof;
                uint32_t r[4];
                ldm4(r, hiB + eo*2u);
                bhi[2*p][0] = r[0]; bhi[2*p][1] = r[1];
                bhi[2*p+1][0] = r[2]; bhi[2*p+1][1] = r[3];
                ldm4(r, loB + eo*2u);
                blo[2*p][0] = r[0]; blo[2*p][1] = r[1];
                blo[2*p+1][0] = r[2]; blo[2*p+1][1] = r[3];
            }
            #pragma unroll
            for (int a = 0; a < 2; a++)
                #pragma unroll
                for (int nt = 0; nt < 8; nt++) {
                    mma16816(acc_hh[a][nt], ahi[a], bhi[nt]);
                    mma16816(acc_q[a][nt],  ahi[a], blo[nt]);
                }
        }

        if (ch < 15) {
            char* dsth = gsm + ((ch + 1) & 1)*36864;
            #pragma unroll
            for (int j = 0; j < 8; j++) {
                float4 v = pref[j];
                ps += (v.x + v.y) + (v.z + v.w);
                __nv_bfloat16 hx = __float2bfloat16(v.x), hy = __float2bfloat16(v.y),
                              hz = __float2bfloat16(v.z), hw = __float2bfloat16(v.w);
                uint32_t off = wo + 8u*j;
                *(uint2*)(dsth + off) = make_uint2(bfp(hx, hy), bfp(hz, hw));
                *(uint2*)(dsth + 18432 + off) = make_uint2(
                    bfp2(v.x - __bfloat162float(hx), v.y - __bfloat162float(hy)),
                    bfp2(v.z - __bfloat162float(hz), v.w - __bfloat162float(hw)));
            }
            if (ch < 14) {
                const float4* src = (const float4*)(rowbase + (long)((ch + 2)*2)*Ww);
                #pragma unroll
                for (int j = 0; j < 8; j++) pref[j] = src[j];
            }
        }
        __syncthreads();
    }

    // epilogue: G = HH + Q + Q^T
    {
        float* Qs = (float*)gsm;
        int grp = lane >> 2, tix = lane & 3;
        #pragma unroll
        for (int a = 0; a < 2; a++)
            #pragma unroll
            for (int nt = 0; nt < 8; nt++) {
                int r0 = m0 + a*16 + grp, cc = n0 + nt*8 + tix*2;
                Qs[r0*132 + cc]       = acc_q[a][nt][0];
                Qs[r0*132 + cc + 1]   = acc_q[a][nt][1];
                Qs[(r0+8)*132 + cc]   = acc_q[a][nt][2];
                Qs[(r0+8)*132 + cc+1] = acc_q[a][nt][3];
            }
        __syncthreads();
        float* Gout = dG + (long)(s*NT + t)*(Cc*Cc);
        #pragma unroll
        for (int a = 0; a < 2; a++)
            #pragma unroll
            for (int nt = 0; nt < 8; nt++) {
                int r0 = m0 + a*16 + grp, cc = n0 + nt*8 + tix*2;
                float2 v0, v1;
                v0.x = acc_hh[a][nt][0] + acc_q[a][nt][0] + Qs[cc*132 + r0];
                v0.y = acc_hh[a][nt][1] + acc_q[a][nt][1] + Qs[(cc+1)*132 + r0];
                v1.x = acc_hh[a][nt][2] + acc_q[a][nt][2] + Qs[cc*132 + r0 + 8];
                v1.y = acc_hh[a][nt][3] + acc_q[a][nt][3] + Qs[(cc+1)*132 + r0 + 8];
                *(float2*)(Gout + (long)r0*128 + cc)       = v0;
                *(float2*)(Gout + (long)(r0 + 8)*128 + cc) = v1;
            }
    }

    {
        float tot = ps + __shfl_xor_sync(0xffffffffu, ps, 1);
        if (half == 0) dS[(s*NT + t)*Cc + c0] = tot;
    }
}

// ---------------------------------------------------------------------------
// Kernel B (R8 scalar FFMA2 version): M = W1 G W2^T + rank-1 bias terms;
// u = l2norm; A = W_out u -> dAh/dAl as bf16 hi/lo, layout [o][k]
// ---------------------------------------------------------------------------
__global__ __launch_bounds__(256) void mid_kernel(
    const float* __restrict__ W1a, const float* __restrict__ B1a,
    const float* __restrict__ W2a, const float* __restrict__ B2a,
    const float* __restrict__ Wouta,
    const float* __restrict__ W1b, const float* __restrict__ B1b,
    const float* __restrict__ W2b, const float* __restrict__ B2b,
    const float* __restrict__ Woutb)
{
    extern __shared__ float sm[];
    float* sG  = sm;            // 128*132
    float* sW  = sm + 16896;    // 128*132
    float* sT  = sm + 33792;    // 128*132
    float* sS  = sm + 50688;    // 128
    float* w1s = sm + 50816;    // 128
    float* w2s = sm + 50944;    // 64
    float* nk  = sm + 51008;    // 64

    int s = blockIdx.y;
    const float* W1   = s ? W1b   : W1a;
    const float* B1   = s ? B1b   : B1a;
    const float* W2   = s ? W2b   : W2a;
    const float* B2   = s ? B2b   : B2a;
    const float* Wout = s ? Woutb : Wouta;

    int t = blockIdx.x, tid = threadIdx.x;
    int ty = tid >> 4, tx = tid & 15;
    const float* Gsrc = dG + (long)(s*NT + t)*(Cc*Cc);

    for (int idx = tid; idx < 16384; idx += 256)
        sG[(idx >> 7)*132 + (idx & 127)] = Gsrc[idx];
    for (int idx = tid; idx < 16384; idx += 256)
        sW[(idx & 127)*132 + (idx >> 7)] = W1[idx];      // W1^T[c][o]
    if (tid < 128) sS[tid] = dS[(s*NT + t)*Cc + tid];
    __syncthreads();

    if (tid < 128) {                                      // w1s = W1 s
        float a = 0.f;
        for (int j = 0; j < 128; j++) a = fmaf(sW[j*132 + tid], sS[j], a);
        w1s[tid] = a;
    }

    // T1 = W1 @ G  (store transposed: sT[col][row])
    {
        int i0 = ty*8, c0 = tx*8;
        u64t acc[8][4];
        #pragma unroll
        for (int u = 0; u < 8; u++)
            #pragma unroll
            for (int v = 0; v < 4; v++) acc[u][v] = 0ull;
        for (int j = 0; j < 128; j++) {
            const float* wr = sW + j*132;
            const float* gr = sG + j*132;
            float4 a03 = *(const float4*)(wr + i0);
            float4 a47 = *(const float4*)(wr + i0 + 4);
            ulonglong2 b01 = *(const ulonglong2*)(gr + c0);
            ulonglong2 b23 = *(const ulonglong2*)(gr + c0 + 4);
            u64t as[8] = { f2splat(a03.x), f2splat(a03.y), f2splat(a03.z), f2splat(a03.w),
                           f2splat(a47.x), f2splat(a47.y), f2splat(a47.z), f2splat(a47.w) };
            #pragma unroll
            for (int u = 0; u < 8; u++) {
                f2fma(acc[u][0], as[u], b01.x);
                f2fma(acc[u][1], as[u], b01.y);
                f2fma(acc[u][2], as[u], b23.x);
                f2fma(acc[u][3], as[u], b23.y);
            }
        }
        #pragma unroll
        for (int u = 0; u < 8; u++)
            #pragma unroll
            for (int v = 0; v < 4; v++) {
                float e0, e1; f2unpack(acc[u][v], e0, e1);
                sT[(c0+2*v  )*132 + i0 + u] = e0;
                sT[(c0+2*v+1)*132 + i0 + u] = e1;
            }
    }
    __syncthreads();

    for (int idx = tid; idx < 8192; idx += 256)           // W2^T[c][k]
        sW[(idx & 127)*132 + (idx >> 7)] = W2[idx];
    __syncthreads();
    if (tid < 64) {                                       // w2s = W2 s
        float a = 0.f;
        for (int c = 0; c < 128; c++) a = fmaf(sW[c*132 + tid], sS[c], a);
        w2s[tid] = a;
    }
    __syncthreads();

    // M = T1 @ W2^T + biases -> sG[c][k]
    {
        int i0 = ty*8, k0 = tx*4;
        u64t acc[8][2];
        #pragma unroll
        for (int u = 0; u < 8; u++) { acc[u][0] = 0ull; acc[u][1] = 0ull; }
        for (int c = 0; c < 128; c++) {
            const float* tr = sT + c*132;
            float4 a03 = *(const float4*)(tr + i0);
            float4 a47 = *(const float4*)(tr + i0 + 4);
            ulonglong2 bq = *(const ulonglong2*)(sW + c*132 + k0);
            u64t as[8] = { f2splat(a03.x), f2splat(a03.y), f2splat(a03.z), f2splat(a03.w),
                           f2splat(a47.x), f2splat(a47.y), f2splat(a47.z), f2splat(a47.w) };
            #pragma unroll
            for (int u = 0; u < 8; u++) {
                f2fma(acc[u][0], as[u], bq.x);
                f2fma(acc[u][1], as[u], bq.y);
            }
        }
        float b2v[4];
        #pragma unroll
        for (int v = 0; v < 4; v++) b2v[v] = B2[k0+v];
        #pragma unroll
        for (int u = 0; u < 8; u++) {
            float b1v = B1[i0+u];
            float m0, m1, m2, m3;
            f2unpack(acc[u][0], m0, m1);
            f2unpack(acc[u][1], m2, m3);
            float w1u = w1s[i0+u];
            sG[(i0+u)*132 + k0+0] = m0 + w1u*b2v[0] + b1v*w2s[k0+0] + 1024.f*b1v*b2v[0];
            sG[(i0+u)*132 + k0+1] = m1 + w1u*b2v[1] + b1v*w2s[k0+1] + 1024.f*b1v*b2v[1];
            sG[(i0+u)*132 + k0+2] = m2 + w1u*b2v[2] + b1v*w2s[k0+2] + 1024.f*b1v*b2v[2];
            sG[(i0+u)*132 + k0+3] = m3 + w1u*b2v[3] + b1v*w2s[k0+3] + 1024.f*b1v*b2v[3];
        }
    }
    __syncthreads();

    if (tid < 64) {                                       // column L2 norms
        float ss = 0.f;
        for (int c = 0; c < 128; c++) { float v = sG[c*132 + tid]; ss = fmaf(v, v, ss); }
        nk[tid] = 1.f / (1e-6f + sqrtf(ss));
    }
    __syncthreads();

    for (int idx = tid; idx < 8192; idx += 256) {         // u = M * invnorm
        int c = idx >> 6, kx = idx & 63;
        sG[c*132 + kx] *= nk[kx];
    }
    for (int idx = tid; idx < 16384; idx += 256)          // Wout^T[c][o]
        sW[(idx & 127)*132 + (idx >> 7)] = Wout[idx];
    __syncthreads();

    // A = Wout @ u  -> write bf16 hi/lo A[o][k]
    {
        int o0 = ty*8, k0 = tx*4;
        u64t acc[4][4];
        #pragma unroll
        for (int kk = 0; kk < 4; kk++)
            #pragma unroll
            for (int v = 0; v < 4; v++) acc[kk][v] = 0ull;
        for (int c = 0; c < 128; c++) {
            const float* wr = sW + c*132;
            ulonglong2 a01 = *(const ulonglong2*)(wr + o0);
            ulonglong2 a23 = *(const ulonglong2*)(wr + o0 + 4);
            float4 bq = *(const float4*)(sG + c*132 + k0);
            u64t bs[4] = { f2splat(bq.x), f2splat(bq.y), f2splat(bq.z), f2splat(bq.w) };
            #pragma unroll
            for (int kk = 0; kk < 4; kk++) {
                f2fma(acc[kk][0], a01.x, bs[kk]);
                f2fma(acc[kk][1], a01.y, bs[kk]);
                f2fma(acc[kk][2], a23.x, bs[kk]);
                f2fma(acc[kk][3], a23.y, bs[kk]);
            }
        }
        ush* AH = dAh + ((long)(s*NT + t) << 13);
        ush* AL = dAl + ((long)(s*NT + t) << 13);
        #pragma unroll
        for (int kk = 0; kk < 4; kk++)
            #pragma unroll
            for (int v = 0; v < 4; v++) {
                float e0, e1; f2unpack(acc[kk][v], e0, e1);
                int k = k0 + kk;
                __nv_bfloat16 h0 = __float2bfloat16(e0);
                __nv_bfloat16 h1 = __float2bfloat16(e1);
                AH[(o0+2*v  )*64 + k] = __bfloat16_as_ushort(h0);
                AH[(o0+2*v+1)*64 + k] = __bfloat16_as_ushort(h1);
                AL[(o0+2*v  )*64 + k] = __bfloat16_as_ushort(__float2bfloat16(e0 - __bfloat162float(h0)));
                AL[(o0+2*v+1)*64 + k] = __bfloat16_as_ushort(__float2bfloat16(e1 - __bfloat162float(h1)));
            }
    }
}

// ---------------------------------------------------------------------------
// Kernel C (R8 HMMA version): per (tile, half): V = softmax_K(Wv [X1;X2] + bv),
// Out1 = A1 V, Out2 = A2 V. 8 chunks of 64 L-cols. 3-product hi/lo split.
// ---------------------------------------------------------------------------
__global__ __launch_bounds__(256) void out_kernel(const float* __restrict__ x1,
                                                  const float* __restrict__ x2,
                                                  const float* __restrict__ Wv,
                                                  const float* __restrict__ bv,
                                                  float* __restrict__ out1,
                                                  float* __restrict__ out2)
{
    extern __shared__ char osm[];
    ush*   sWvH  = (ush*)osm;                  // [64][264]
    ush*   sWvL  = sWvH + 64*264;
    ush*   sAH   = sWvL + 64*264;              // [2][128][72]
    ush*   sAL   = sAH + 2*128*72;
    ush*   sXH   = sAL + 2*128*72;             // [128][72]
    ush*   sXL   = sXH + 128*72;
    ush*   sVH   = sXL + 128*72;               // [64][72]
    ush*   sVL   = sVH + 64*72;
    float* sVraw = (float*)(sVL + 64*72);      // [64][72]
    float* sbv   = sVraw + 64*72;              // 64

    uint32_t uWvH = s2u(sWvH), uWvL = s2u(sWvL);
    uint32_t uAH = s2u(sAH), uAL = s2u(sAL);
    uint32_t uXH = s2u(sXH), uXL = s2u(sXL);
    uint32_t uVH = s2u(sVH), uVL = s2u(sVL);

    int t = blockIdx.x, halfy = blockIdx.y;
    int b  = t >> 6, q = t & 63;
    int pi = q >> 3, pj = q & 7;
    long base0 = (long)b*Cc*HW + (long)(pi*32)*Ww + pj*32;
    int li0 = halfy*16;

    int tid = threadIdx.x, wid = tid >> 5, lane = tid & 31;

    // ---- load Wv hi/lo ----
    for (int idx = tid; idx < 16384; idx += 256) {
        int r = idx >> 8, c = idx & 255;
        float v = Wv[idx];
        __nv_bfloat16 h = __float2bfloat16(v);
        sWvH[r*264 + c] = __bfloat16_as_ushort(h);
        sWvL[r*264 + c] = __bfloat16_as_ushort(__float2bfloat16(v - __bfloat162float(h)));
    }
    // ---- load A hi/lo (both streams) ----
    {
        const ush* A1h = dAh + ((long)t << 13);
        const ush* A2h = dAh + ((long)(NT + t) << 13);
        const ush* A1l = dAl + ((long)t << 13);
        const ush* A2l = dAl + ((long)(NT + t) << 13);
        for (int idx = tid; idx < 8192; idx += 256) {
            int o = idx >> 6, k = idx & 63;
            sAH[o*72 + k]        = A1h[idx];
            sAH[9216 + o*72 + k] = A2h[idx];
            sAL[o*72 + k]        = A1l[idx];
            sAL[9216 + o*72 + k] = A2l[idx];
        }
    }
    if (tid < 64) sbv[tid] = bv[tid];

    // lane addressing
    uint32_t aRow = (uint32_t)(lane & 15);
    uint32_t aKof = (uint32_t)((lane >> 4) << 3);
    uint32_t g = (uint32_t)(lane >> 3), rr8 = (uint32_t)(lane & 7);
    uint32_t tKrow = ((g & 1u) << 3) + rr8;     // k offset within k16 block
    uint32_t tNcol = (g >> 1) << 3;             // n offset within n16 block
    int grp = lane >> 2, tix = lane & 3;

    // X loader mapping: thread handles channel c0, local row h2
    int c0 = tid >> 1, h2 = tid & 1;
    const float* x1base = x1 + base0 + (long)c0*HW;
    const float* x2base = x2 + base0 + (long)c0*HW;
    uint32_t xwo = (uint32_t)c0*72u + (uint32_t)h2*32u;

    // V GEMM warp tiling: m0 over k-dim(64), n0 over l(64)
    int vm0 = (wid & 3)*16, vn0 = (wid >> 2)*32;
    // out GEMM warp tiling
    int st = wid >> 2, om0 = (wid & 3)*32;
    uint32_t uA_H = uAH + (uint32_t)st*9216u*2u;
    uint32_t uA_L = uAL + (uint32_t)st*9216u*2u;
    float* outp = st ? out2 : out1;

    float4 pref[8];
    {
        const float4* src = (const float4*)(x1base + (long)(li0 + h2)*Ww);
        #pragma unroll
        for (int j = 0; j < 8; j++) pref[j] = src[j];
    }
    __syncthreads();

    for (int ch = 0; ch < 8; ch++) {
        int lrow = li0 + 2*ch;
        // step1: store X1 chunk
        #pragma unroll
        for (int j = 0; j < 8; j++) {
            float4 v = pref[j];
            __nv_bfloat16 hx = __float2bfloat16(v.x), hy = __float2bfloat16(v.y),
                          hz = __float2bfloat16(v.z), hw = __float2bfloat16(v.w);
            uint32_t off = (xwo + 4u*j)*2u;
            *(uint2*)((char*)sXH + off) = make_uint2(bfp(hx, hy), bfp(hz, hw));
            *(uint2*)((char*)sXL + off) = make_uint2(
                bfp2(v.x - __bfloat162float(hx), v.y - __bfloat162float(hy)),
                bfp2(v.z - __bfloat162float(hz), v.w - __bfloat162float(hw)));
        }
        __syncthreads();

        // step2: prefetch X2; V GEMM phase 0 (Wv cols 0..127 on X1)
        {
            const float4* src = (const float4*)(x2base + (long)(lrow + h2)*Ww);
            #pragma unroll
            for (int j = 0; j < 8; j++) pref[j] = src[j];
        }
        float accV[4][4];
        #pragma unroll
        for (int nt = 0; nt < 4; nt++)
            #pragma unroll
            for (int e = 0; e < 4; e++) accV[nt][e] = 0.f;

        #pragma unroll 2
        for (int ks = 0; ks < 8; ks++) {
            uint32_t kx = (uint32_t)(ks*16);
            uint32_t ah[4], al[4], bh[8], bl[8];
            uint32_t ao = ((uint32_t)vm0 + aRow)*264u + kx + aKof;
            ldm4(ah, uWvH + ao*2u);
            ldm4(al, uWvL + ao*2u);
            uint32_t bo0 = (kx + tKrow)*72u + (uint32_t)vn0 + tNcol;
            ldm4t(bh,     uXH + bo0*2u);
            ldm4t(bh + 4, uXH + (bo0 + 16u)*2u);
            ldm4t(bl,     uXL + bo0*2u);
            ldm4t(bl + 4, uXL + (bo0 + 16u)*2u);
            #pragma unroll
            for (int nt = 0; nt < 4; nt++) {
                mma16816(accV[nt], ah, bh + 2*nt);
                mma16816(accV[nt], ah, bl + 2*nt);
                mma16816(accV[nt], al, bh + 2*nt);
            }
        }
        __syncthreads();

        // step3: store X2 chunk
        #pragma unroll
        for (int j = 0; j < 8; j++) {
            float4 v = pref[j];
            __nv_bfloat16 hx = __float2bfloat16(v.x), hy = __float2bfloat16(v.y),
                          hz = __float2bfloat16(v.z), hw = __float2bfloat16(v.w);
            uint32_t off = (xwo + 4u*j)*2u;
            *(uint2*)((char*)sXH + off) = make_uint2(bfp(hx, hy), bfp(hz, hw));
            *(uint2*)((char*)sXL + off) = make_uint2(
                bfp2(v.x - __bfloat162float(hx), v.y - __bfloat162float(hy)),
                bfp2(v.z - __bfloat162float(hz), v.w - __bfloat162float(hw)));
        }
        __syncthreads();

        // step4: V GEMM phase 1 (Wv cols 128..255 on X2)
        #pragma unroll 2
        for (int ks = 0; ks < 8; ks++) {
            uint32_t kx = (uint32_t)(ks*16);
            uint32_t ah[4], al[4], bh[8], bl[8];
            uint32_t ao = ((uint32_t)vm0 + aRow)*264u + 128u + kx + aKof;
            ldm4(ah, uWvH + ao*2u);
            ldm4(al, uWvL + ao*2u);
            uint32_t bo0 = (kx + tKrow)*72u + (uint32_t)vn0 + tNcol;
            ldm4t(bh,     uXH + bo0*2u);
            ldm4t(bh + 4, uXH + (bo0 + 16u)*2u);
            ldm4t(bl,     uXL + bo0*2u);
            ldm4t(bl + 4, uXL + (bo0 + 16u)*2u);
            #pragma unroll
            for (int nt = 0; nt < 4; nt++) {
                mma16816(accV[nt], ah, bh + 2*nt);
                mma16816(accV[nt], ah, bl + 2*nt);
                mma16816(accV[nt], al, bh + 2*nt);
            }
        }
        // store V_raw + bias
        {
            float bv0 = sbv[vm0 + grp], bv1 = sbv[vm0 + grp + 8];
            #pragma unroll
            for (int nt = 0; nt < 4; nt++) {
                int col = vn0 + nt*8 + tix*2;
                float2 v0; v0.x = accV[nt][0] + bv0; v0.y = accV[nt][1] + bv0;
                float2 v1; v1.x = accV[nt][2] + bv1; v1.y = accV[nt][3] + bv1;
                *(float2*)(sVraw + (vm0 + grp)*72 + col)     = v0;
                *(float2*)(sVraw + (vm0 + grp + 8)*72 + col) = v1;
            }
        }
        __syncthreads();

        // step5: softmax over k per column; emit V hi/lo bf16
        {
            int col = wid*8 + (lane >> 2);
            int kg = lane & 3;
            float vals[16];
            float m = -1e30f;
            #pragma unroll
            for (int i = 0; i < 16; i++) {
                vals[i] = sVraw[(i*4 + kg)*72 + col];
                m = fmaxf(m, vals[i]);
            }
            m = fmaxf(m, __shfl_xor_sync(0xffffffffu, m, 1));
            m = fmaxf(m, __shfl_xor_sync(0xffffffffu, m, 2));
            float ssum = 0.f;
            #pragma unroll
            for (int i = 0; i < 16; i++) { float e = __expf(vals[i] - m); vals[i] = e; ssum += e; }
            ssum += __shfl_xor_sync(0xffffffffu, ssum, 1);
            ssum += __shfl_xor_sync(0xffffffffu, ssum, 2);
            float inv = 1.f / ssum;
            #pragma unroll
            for (int i = 0; i < 16; i++) {
                float v = vals[i]*inv;
                __nv_bfloat16 h = __float2bfloat16(v);
                int idx = (i*4 + kg)*72 + col;
                sVH[idx] = __bfloat16_as_ushort(h);
                sVL[idx] = __bfloat16_as_ushort(__float2bfloat16(v - __bfloat162float(h)));
            }
        }
        __syncthreads();

        // step6: out GEMM + epilogue; prefetch next X1
        {
            float accO[2][8][4];
            #pragma unroll
            for (int a = 0; a < 2; a++)
                #pragma unroll
                for (int nt = 0; nt < 8; nt++)
                    #pragma unroll
                    for (int e = 0; e < 4; e++) accO[a][nt][e] = 0.f;

            #pragma unroll
            for (int ks = 0; ks < 4; ks++) {
                uint32_t k0 = (uint32_t)(ks*16);
                uint32_t ah[2][4], al[2][4], bh[16], bl[16];
                #pragma unroll
                for (int a = 0; a < 2; a++) {
                    uint32_t ao = ((uint32_t)(om0 + a*16) + aRow)*72u + k0 + aKof;
                    ldm4(ah[a], uA_H + ao*2u);
                    ldm4(al[a], uA_L + ao*2u);
                }
                #pragma unroll
                for (int qq = 0; qq < 4; qq++) {
                    uint32_t bo = (k0 + tKrow)*72u + (uint32_t)(qq*16) + tNcol;
                    ldm4t(bh + 4*qq, uVH + bo*2u);
                    ldm4t(bl + 4*qq, uVL + bo*2u);
                }
                #pragma unroll
                for (int a = 0; a < 2; a++)
                    #pragma unroll
                    for (int nt = 0; nt < 8; nt++) {
                        const uint32_t* ph = bh + 4*(nt >> 1) + 2*(nt & 1);
                        const uint32_t* pl = bl + 4*(nt >> 1) + 2*(nt & 1);
                        mma16816(accO[a][nt], ah[a], ph);
                        mma16816(accO[a][nt], ah[a], pl);
                        mma16816(accO[a][nt], al[a], ph);
                    }
            }

            if (ch < 7) {
                const float4* src = (const float4*)(x1base + (long)(lrow + 2 + h2)*Ww);
                #pragma unroll
                for (int j = 0; j < 8; j++) pref[j] = src[j];
            }

            #pragma unroll
            for (int a = 0; a < 2; a++)
                #pragma unroll
                for (int nt = 0; nt < 8; nt++) {
                    int o = om0 + a*16 + grp;
                    int l = nt*8 + tix*2;
                    int lr = l >> 5, lj = l & 31;
                    long gaddr = ((long)(b*Cc + o)*Hh + (pi*32 + lrow + lr))*Ww + pj*32 + lj;
                    float2 v0; v0.x = accO[a][nt][0]; v0.y = accO[a][nt][1];
                    float2 v1; v1.x = accO[a][nt][2]; v1.y = accO[a][nt][3];
                    *(float2*)(outp + gaddr)              = v0;
                    *(float2*)(outp + gaddr + 8l*HW)      = v1;
                }
        }
        __syncthreads();
    }
}

extern "C" void kernel_launch(void* const* d_in, const int* in_sizes, int n_in,
                              void* d_out, int out_size)
{
    const float* x1     = (const float*)d_in[0];
    const float* x2     = (const float*)d_in[1];
    const float* w_v    = (const float*)d_in[2];
    const float* b_v    = (const float*)d_in[3];
    const float* w1_1   = (const float*)d_in[4];
    const float* b1_1   = (const float*)d_in[5];
    const float* w2_1   = (const float*)d_in[6];
    const float* b2_1   = (const float*)d_in[7];
    const float* w_out1 = (const float*)d_in[8];
    const float* w1_2   = (const float*)d_in[9];
    const float* b1_2   = (const float*)d_in[10];
    const float* w2_2   = (const float*)d_in[11];
    const float* b2_2   = (const float*)d_in[12];
    const float* w_out2 = (const float*)d_in[13];
    (void)in_sizes; (void)n_in; (void)out_size;

    float* out1 = (float*)d_out;
    float* out2 = out1 + (size_t)Bb*Cc*HW;

    cudaFuncSetAttribute(gram_kernel, cudaFuncAttributeMaxDynamicSharedMemorySize, GRAM2_SMEM);
    cudaFuncSetAttribute(mid_kernel, cudaFuncAttributeMaxDynamicSharedMemorySize, MID_SMEM);
    cudaFuncSetAttribute(out_kernel, cudaFuncAttributeMaxDynamicSharedMemorySize, OUT2_SMEM);

    gram_kernel<<<dim3(NT, 2), 256, GRAM2_SMEM>>>(x1, x2);
    mid_kernel<<<dim3(NT, 2), 256, MID_SMEM>>>(w1_1, b1_1, w2_1, b2_1, w_out1,
                                               w1_2, b1_2, w2_2, b2_2, w_out2);
    out_kernel<<<dim3(NT, 2), 256, OUT2_SMEM>>>(x1, x2, w_v, b_v, out1, out2);
}